// round 14
// baseline (speedup 1.0000x reference)
#include <cuda_runtime.h>
#include <cuda_bf16.h>

// Problem constants (fixed by the dataset)
#define B_TOT   1024
#define S_LEN   2048
#define F_IN    9
#define NOUT    8
#define UDIM    256
#define LBK     3
#define DDIM    11      // NOUT + 3
#define XDIM    33      // LBK * DDIM
#define H1DIM   512     // 2*U
#define T_OUT   2044    // S - 1 - LBK
#define M_ROWS  8
#define NCTA    128     // NCTA * M_ROWS == B_TOT
#define NTHREADS 512    // 16 warps

typedef unsigned long long u64;

// Blackwell packed fp32 FMA: (a.lo*b.lo+c.lo, a.hi*b.hi+c.hi)
__device__ __forceinline__ u64 ffma2(u64 a, u64 b, u64 c) {
    u64 d;
    asm("fma.rn.f32x2 %0, %1, %2, %3;" : "=l"(d) : "l"(a), "l"(b), "l"(c));
    return d;
}
__device__ __forceinline__ float2 unpack2(u64 v) {
    float2 f;
    asm("mov.b64 {%0, %1}, %2;" : "=f"(f.x), "=f"(f.y) : "l"(v));
    return f;
}
__device__ __forceinline__ float tanh_fast(float x) {
    float y;
    asm("tanh.approx.f32 %0, %1;" : "=f"(y) : "f"(x));
    return y;
}

// Packed dec2 weights (built once per launch by pack_kernel):
//  g_wd2a[blk][lane][n] = wd2[(blk*32+lane)*8 + n]      n = 0..3
//  g_wd2b[blk][lane][n] = wd2[(blk*32+lane)*8 + 4 + n]  n = 0..3
__device__ float g_wd2a[16 * 32 * 4];
__device__ float g_wd2b[16 * 32 * 4];

__global__ void pack_kernel(const float* __restrict__ wd2) {
    int idx = blockIdx.x * blockDim.x + threadIdx.x;   // over 512*8
    if (idx < 512 * 8) {
        int k = idx >> 3, n = idx & 7;
        int blk = k >> 5, l = k & 31;
        float v = wd2[idx];
        if (n < 4) g_wd2a[(blk * 32 + l) * 4 + n] = v;
        else       g_wd2b[(blk * 32 + l) * 4 + (n - 4)] = v;
    }
}

// Dynamic SMEM layout (in floats)
#define OFF_BIG   0            // [8][1024]  dup h1 (enc1 out / enc2 in)
#define OFF_H     8192         // [8][512]   dup s_h (enc2 out / upd+beta in)
#define OFF_COMB  12288        // [8][528]   dup comb (LN2 out / dec1 in; [512]=ect dup)
#define OFF_U     16512        // [8][512]   plain: u (pre-LN) then t1 (dec1 out / dec2 in)
#define OFF_XX    20608        // [8][36]    plain post-LN1 x
#define OFF_WIN   20896        // [8][3][8]
#define OFF_Y     21088        // [8][8]
#define OFF_GP    21152        // [8][8]
#define SMEM_FLOATS 21216
#define SMEM_BYTES  (SMEM_FLOATS * 4)

__global__ __launch_bounds__(NTHREADS, 1)
void dps_kernel(const float* __restrict__ inputs,
                const float* __restrict__ ln1_g, const float* __restrict__ ln1_b,
                const float* __restrict__ w1,    const float* __restrict__ b1,
                const float* __restrict__ w2,    const float* __restrict__ b2,
                const float* __restrict__ wu,    const float* __restrict__ bu,
                const float* __restrict__ ln2_g, const float* __restrict__ ln2_b,
                const float* __restrict__ wbeta,
                const float* __restrict__ wd1,   const float* __restrict__ bd1,
                const float* __restrict__ wd2,   const float* __restrict__ bd2,
                const int*   __restrict__ fix,
                float* __restrict__ out)
{
    extern __shared__ float smem[];
    float (*s_big)[1024] = (float(*)[1024])(smem + OFF_BIG);   // dup
    float (*s_h)[512]    = (float(*)[512])(smem + OFF_H);      // dup
    float (*s_comb)[528] = (float(*)[528])(smem + OFF_COMB);   // dup
    float (*s_u)[512]    = (float(*)[512])(smem + OFF_U);      // plain u / t1
    float (*s_xx)[36]    = (float(*)[36])(smem + OFF_XX);
    float (*s_win)[LBK][NOUT] = (float(*)[LBK][NOUT])(smem + OFF_WIN);
    float (*s_y)[NOUT]   = (float(*)[NOUT])(smem + OFF_Y);
    float (*s_gp)[NOUT]  = (float(*)[NOUT])(smem + OFF_GP);

    const int tid  = threadIdx.x;
    const int lane = tid & 31;
    const int wid  = tid >> 5;
    const int row0 = blockIdx.x * M_ROWS;

    const int fix0 = fix[0];
    const int fix1 = fix[1];

    const float4* w2v  = (const float4*)w2;    // [512][64] j-quads
    const float4* wuv  = (const float4*)wu;    // [256][64]
    const float4* wd1v = (const float4*)wd1;   // [257][128]

    // ---- init window
    for (int idx = tid; idx < M_ROWS * LBK * NOUT; idx += NTHREADS) {
        int m = idx / (LBK * NOUT);
        int r = idx % (LBK * NOUT);
        int t = r / NOUT, n = r % NOUT;
        s_win[m][t][n] = inputs[((size_t)(row0 + m) * S_LEN + t) * F_IN + 1 + n];
    }
    __syncthreads();

    for (int i = LBK; i < S_LEN - 1; ++i) {
        // ================= Phase A: build x, LayerNorm1 ============================
        if (tid < M_ROWS * LBK) {
            int m = tid / LBK, t = tid % LBK;
            int s = i - LBK + t;
            size_t base = ((size_t)(row0 + m) * S_LEN + s) * F_IN;
            float ld = inputs[base];
            float df = (s > 0) ? (ld - inputs[base - F_IN]) : 0.0f;
            float x[DDIM];
            x[0] = ld; x[1] = ld; x[2] = df;
            #pragma unroll
            for (int n = 0; n < NOUT; ++n) x[3 + n] = s_win[m][t][n];
            float mean = 0.f;
            #pragma unroll
            for (int d = 0; d < DDIM; ++d) mean += x[d];
            mean *= (1.0f / DDIM);
            float var = 0.f;
            #pragma unroll
            for (int d = 0; d < DDIM; ++d) { float c = x[d] - mean; var += c * c; }
            var *= (1.0f / DDIM);
            float rs = rsqrtf(var + 1e-3f);
            #pragma unroll
            for (int d = 0; d < DDIM; ++d)
                s_xx[m][t * DDIM + d] = (x[d] - mean) * rs * ln1_g[d] + ln1_b[d];
        }
        __syncthreads();

        // ================= Phase B: enc1 (33 -> 512) + tanh, dup output ============
        {
            float acc[M_ROWS];
            #pragma unroll
            for (int m = 0; m < M_ROWS; ++m) acc[m] = 0.f;
            const int j = tid;
            #pragma unroll 4
            for (int kk = 0; kk < 32; kk += 4) {
                float wv0 = w1[(kk + 0) * H1DIM + j];
                float wv1 = w1[(kk + 1) * H1DIM + j];
                float wv2 = w1[(kk + 2) * H1DIM + j];
                float wv3 = w1[(kk + 3) * H1DIM + j];
                #pragma unroll
                for (int m = 0; m < M_ROWS; ++m) {
                    float4 xv = *reinterpret_cast<const float4*>(&s_xx[m][kk]);
                    acc[m] = fmaf(xv.x, wv0, acc[m]);
                    acc[m] = fmaf(xv.y, wv1, acc[m]);
                    acc[m] = fmaf(xv.z, wv2, acc[m]);
                    acc[m] = fmaf(xv.w, wv3, acc[m]);
                }
            }
            {
                float wv = w1[32 * H1DIM + j];
                #pragma unroll
                for (int m = 0; m < M_ROWS; ++m)
                    acc[m] = fmaf(s_xx[m][32], wv, acc[m]);
            }
            float bb = b1[j];
            #pragma unroll
            for (int m = 0; m < M_ROWS; ++m) {
                float v = tanh_fast(acc[m] + bb);
                *reinterpret_cast<float2*>(&s_big[m][2 * j]) = make_float2(v, v);
            }
        }
        __syncthreads();

        // ===== Phase C: enc2 (512 -> 256), FFMA2 j-pairs, 8-way k-split ============
        {
            const int q  = (wid << 2) | (lane & 3);   // 0..63 output quad
            const int sp = lane >> 2;                 // 0..7 split
            const int k0 = sp << 6;                   // 64 k per split
            u64 a01[M_ROWS], a23[M_ROWS];
            #pragma unroll
            for (int m = 0; m < M_ROWS; ++m) { a01[m] = 0; a23[m] = 0; }
            #pragma unroll 2
            for (int kk = k0; kk < k0 + 64; kk += 4) {
                ulonglong2 wp0 = *(const ulonglong2*)&w2v[(kk + 0) * 64 + q];
                ulonglong2 wp1 = *(const ulonglong2*)&w2v[(kk + 1) * 64 + q];
                ulonglong2 wp2 = *(const ulonglong2*)&w2v[(kk + 2) * 64 + q];
                ulonglong2 wp3 = *(const ulonglong2*)&w2v[(kk + 3) * 64 + q];
                #pragma unroll
                for (int m = 0; m < M_ROWS; ++m) {
                    ulonglong2 d01 = *(const ulonglong2*)&s_big[m][2 * kk];
                    ulonglong2 d23 = *(const ulonglong2*)&s_big[m][2 * kk + 4];
                    a01[m] = ffma2(d01.x, wp0.x, a01[m]); a23[m] = ffma2(d01.x, wp0.y, a23[m]);
                    a01[m] = ffma2(d01.y, wp1.x, a01[m]); a23[m] = ffma2(d01.y, wp1.y, a23[m]);
                    a01[m] = ffma2(d23.x, wp2.x, a01[m]); a23[m] = ffma2(d23.x, wp2.y, a23[m]);
                    a01[m] = ffma2(d23.y, wp3.x, a01[m]); a23[m] = ffma2(d23.y, wp3.y, a23[m]);
                }
            }
            float4 acc[M_ROWS];
            #pragma unroll
            for (int m = 0; m < M_ROWS; ++m) {
                float2 p = unpack2(a01[m]), r = unpack2(a23[m]);
                acc[m] = make_float4(p.x, p.y, r.x, r.y);
            }
            #pragma unroll
            for (int m = 0; m < M_ROWS; ++m) {
                #pragma unroll
                for (int o = 4; o <= 16; o <<= 1) {
                    acc[m].x += __shfl_xor_sync(0xffffffffu, acc[m].x, o);
                    acc[m].y += __shfl_xor_sync(0xffffffffu, acc[m].y, o);
                    acc[m].z += __shfl_xor_sync(0xffffffffu, acc[m].z, o);
                    acc[m].w += __shfl_xor_sync(0xffffffffu, acc[m].w, o);
                }
            }
            if (sp == 0) {
                float4 bb = ((const float4*)b2)[q];
                #pragma unroll
                for (int m = 0; m < M_ROWS; ++m) {
                    float v0 = acc[m].x + bb.x, v1 = acc[m].y + bb.y;
                    float v2 = acc[m].z + bb.z, v3 = acc[m].w + bb.w;
                    *reinterpret_cast<float4*>(&s_h[m][8 * q])     = make_float4(v0, v0, v1, v1);
                    *reinterpret_cast<float4*>(&s_h[m][8 * q + 4]) = make_float4(v2, v2, v3, v3);
                }
            }
        }
        __syncthreads();

        // ===== Phase D: beta dot + upd (256 -> 256), FFMA2, 8-way k-split ==========
        if (wid < M_ROWS) {   // ect[m] = h[m] . beta  (dup stride-2 reads)
            int m = wid;
            float p = 0.f;
            for (int k = lane; k < UDIM; k += 32) p = fmaf(s_h[m][2 * k], wbeta[k], p);
            #pragma unroll
            for (int o = 16; o > 0; o >>= 1) p += __shfl_xor_sync(0xffffffffu, p, o);
            if (lane == 0) {
                s_comb[m][512] = p;
                s_comb[m][513] = p;
            }
        }
        {
            const int q  = (wid << 2) | (lane & 3);
            const int sp = lane >> 2;
            const int k0 = sp << 5;                   // 32 k per split
            u64 a01[M_ROWS], a23[M_ROWS];
            #pragma unroll
            for (int m = 0; m < M_ROWS; ++m) { a01[m] = 0; a23[m] = 0; }
            #pragma unroll 2
            for (int kk = k0; kk < k0 + 32; kk += 4) {
                ulonglong2 wp0 = *(const ulonglong2*)&wuv[(kk + 0) * 64 + q];
                ulonglong2 wp1 = *(const ulonglong2*)&wuv[(kk + 1) * 64 + q];
                ulonglong2 wp2 = *(const ulonglong2*)&wuv[(kk + 2) * 64 + q];
                ulonglong2 wp3 = *(const ulonglong2*)&wuv[(kk + 3) * 64 + q];
                #pragma unroll
                for (int m = 0; m < M_ROWS; ++m) {
                    ulonglong2 d01 = *(const ulonglong2*)&s_h[m][2 * kk];
                    ulonglong2 d23 = *(const ulonglong2*)&s_h[m][2 * kk + 4];
                    a01[m] = ffma2(d01.x, wp0.x, a01[m]); a23[m] = ffma2(d01.x, wp0.y, a23[m]);
                    a01[m] = ffma2(d01.y, wp1.x, a01[m]); a23[m] = ffma2(d01.y, wp1.y, a23[m]);
                    a01[m] = ffma2(d23.x, wp2.x, a01[m]); a23[m] = ffma2(d23.x, wp2.y, a23[m]);
                    a01[m] = ffma2(d23.y, wp3.x, a01[m]); a23[m] = ffma2(d23.y, wp3.y, a23[m]);
                }
            }
            float4 acc[M_ROWS];
            #pragma unroll
            for (int m = 0; m < M_ROWS; ++m) {
                float2 p = unpack2(a01[m]), r = unpack2(a23[m]);
                acc[m] = make_float4(p.x, p.y, r.x, r.y);
            }
            #pragma unroll
            for (int m = 0; m < M_ROWS; ++m) {
                #pragma unroll
                for (int o = 4; o <= 16; o <<= 1) {
                    acc[m].x += __shfl_xor_sync(0xffffffffu, acc[m].x, o);
                    acc[m].y += __shfl_xor_sync(0xffffffffu, acc[m].y, o);
                    acc[m].z += __shfl_xor_sync(0xffffffffu, acc[m].z, o);
                    acc[m].w += __shfl_xor_sync(0xffffffffu, acc[m].w, o);
                }
            }
            if (sp == 0) {
                float4 bb = ((const float4*)bu)[q];
                #pragma unroll
                for (int m = 0; m < M_ROWS; ++m)
                    *reinterpret_cast<float4*>(&s_u[m][4 * q]) =
                        make_float4(acc[m].x + bb.x, acc[m].y + bb.y,
                                    acc[m].z + bb.z, acc[m].w + bb.w);   // plain u
            }
        }
        __syncthreads();

        // ================= Phase E: LayerNorm2 (warps 0..7), write dup =============
        if (wid < M_ROWS) {
            int m = wid;
            float v[8];
            float4 a = *reinterpret_cast<const float4*>(&s_u[m][lane * 8]);
            float4 b = *reinterpret_cast<const float4*>(&s_u[m][lane * 8 + 4]);
            v[0]=a.x; v[1]=a.y; v[2]=a.z; v[3]=a.w;
            v[4]=b.x; v[5]=b.y; v[6]=b.z; v[7]=b.w;
            float sum = 0.f, sq = 0.f;
            #pragma unroll
            for (int q = 0; q < 8; ++q) { sum += v[q]; sq = fmaf(v[q], v[q], sq); }
            #pragma unroll
            for (int o = 16; o > 0; o >>= 1) {
                sum += __shfl_xor_sync(0xffffffffu, sum, o);
                sq  += __shfl_xor_sync(0xffffffffu, sq, o);
            }
            float mean = sum * (1.0f / UDIM);
            float var  = sq * (1.0f / UDIM) - mean * mean;
            float rs = rsqrtf(var + 1e-3f);
            #pragma unroll
            for (int qq = 0; qq < 8; qq += 2) {
                int k = lane * 8 + qq;
                float n0 = (v[qq]     - mean) * rs * ln2_g[k]     + ln2_b[k];
                float n1 = (v[qq + 1] - mean) * rs * ln2_g[k + 1] + ln2_b[k + 1];
                *reinterpret_cast<float4*>(&s_comb[m][2 * k]) = make_float4(n0, n0, n1, n1);
            }
        }
        __syncthreads();

        // ===== Phase F: dec1 (257 -> 512) + tanh, FFMA2, 4-way k-split =============
        {
            const int q  = (wid << 3) | (lane & 7);   // 0..127
            const int sp = lane >> 3;                 // 0..3
            const int k0 = sp << 6;                   // 64 k per split
            u64 a01[M_ROWS], a23[M_ROWS];
            #pragma unroll
            for (int m = 0; m < M_ROWS; ++m) { a01[m] = 0; a23[m] = 0; }
            #pragma unroll 2
            for (int kk = k0; kk < k0 + 64; kk += 4) {
                ulonglong2 wp0 = *(const ulonglong2*)&wd1v[(kk + 0) * 128 + q];
                ulonglong2 wp1 = *(const ulonglong2*)&wd1v[(kk + 1) * 128 + q];
                ulonglong2 wp2 = *(const ulonglong2*)&wd1v[(kk + 2) * 128 + q];
                ulonglong2 wp3 = *(const ulonglong2*)&wd1v[(kk + 3) * 128 + q];
                #pragma unroll
                for (int m = 0; m < M_ROWS; ++m) {
                    ulonglong2 d01 = *(const ulonglong2*)&s_comb[m][2 * kk];
                    ulonglong2 d23 = *(const ulonglong2*)&s_comb[m][2 * kk + 4];
                    a01[m] = ffma2(d01.x, wp0.x, a01[m]); a23[m] = ffma2(d01.x, wp0.y, a23[m]);
                    a01[m] = ffma2(d01.y, wp1.x, a01[m]); a23[m] = ffma2(d01.y, wp1.y, a23[m]);
                    a01[m] = ffma2(d23.x, wp2.x, a01[m]); a23[m] = ffma2(d23.x, wp2.y, a23[m]);
                    a01[m] = ffma2(d23.y, wp3.x, a01[m]); a23[m] = ffma2(d23.y, wp3.y, a23[m]);
                }
            }
            float4 acc[M_ROWS];
            #pragma unroll
            for (int m = 0; m < M_ROWS; ++m) {
                float2 p = unpack2(a01[m]), r = unpack2(a23[m]);
                acc[m] = make_float4(p.x, p.y, r.x, r.y);
            }
            #pragma unroll
            for (int m = 0; m < M_ROWS; ++m) {
                #pragma unroll
                for (int o = 8; o <= 16; o <<= 1) {
                    acc[m].x += __shfl_xor_sync(0xffffffffu, acc[m].x, o);
                    acc[m].y += __shfl_xor_sync(0xffffffffu, acc[m].y, o);
                    acc[m].z += __shfl_xor_sync(0xffffffffu, acc[m].z, o);
                    acc[m].w += __shfl_xor_sync(0xffffffffu, acc[m].w, o);
                }
            }
            if (sp == 0) {
                float4 wq = wd1v[256 * 128 + q];      // ect column
                float4 bb = ((const float4*)bd1)[q];
                #pragma unroll
                for (int m = 0; m < M_ROWS; ++m) {
                    float e = s_comb[m][512];
                    float v0 = tanh_fast(fmaf(e, wq.x, acc[m].x) + bb.x);
                    float v1 = tanh_fast(fmaf(e, wq.y, acc[m].y) + bb.y);
                    float v2 = tanh_fast(fmaf(e, wq.z, acc[m].z) + bb.z);
                    float v3 = tanh_fast(fmaf(e, wq.w, acc[m].w) + bb.w);
                    *reinterpret_cast<float4*>(&s_u[m][4 * q]) =
                        make_float4(v0, v1, v2, v3);   // t1 plain (overwrites u)
                }
            }
        }
        __syncthreads();

        // ===== Phase G: dec2 (512 -> 8), coalesced k-loop, packed weights ==========
        {
            const int m    = wid & 7;
            const int half = wid >> 3;
            float acc[8];
            #pragma unroll
            for (int n = 0; n < 8; ++n) acc[n] = 0.f;
            #pragma unroll
            for (int kb = 0; kb < 8; ++kb) {
                int blk = half * 8 + kb;
                int k = blk * 32 + lane;
                float s = s_u[m][k];
                float4 wa = *(const float4*)&g_wd2a[(blk * 32 + lane) * 4];
                float4 wb = *(const float4*)&g_wd2b[(blk * 32 + lane) * 4];
                acc[0] = fmaf(s, wa.x, acc[0]); acc[1] = fmaf(s, wa.y, acc[1]);
                acc[2] = fmaf(s, wa.z, acc[2]); acc[3] = fmaf(s, wa.w, acc[3]);
                acc[4] = fmaf(s, wb.x, acc[4]); acc[5] = fmaf(s, wb.y, acc[5]);
                acc[6] = fmaf(s, wb.z, acc[6]); acc[7] = fmaf(s, wb.w, acc[7]);
            }
            #pragma unroll
            for (int o = 16; o > 0; o >>= 1) {
                #pragma unroll
                for (int n = 0; n < 8; ++n)
                    acc[n] += __shfl_xor_sync(0xffffffffu, acc[n], o);
            }
            if (half == 1 && lane == 0) {
                #pragma unroll
                for (int n = 0; n < 8; ++n) s_gp[m][n] = acc[n];
            }
            __syncthreads();
            if (half == 0 && lane == 0) {
                int b = row0 + m;
                size_t ib = ((size_t)b * S_LEN + (i + 1)) * F_IN;
                #pragma unroll
                for (int n = 0; n < 8; ++n) {
                    float y = acc[n] + s_gp[m][n] + bd2[n];
                    if (n == fix0) y = inputs[ib + 1 + fix0];
                    if (n == fix1) y = inputs[ib + 1 + fix1];
                    s_y[m][n] = y;
                    out[(size_t)n * ((size_t)B_TOT * T_OUT) + (size_t)b * T_OUT + (i - LBK)] = y;
                }
            }
        }
        __syncthreads();

        // ---- window shift
        if (tid < M_ROWS * NOUT) {
            int m = tid >> 3, n = tid & 7;
            float a = s_win[m][1][n];
            float b = s_win[m][2][n];
            s_win[m][0][n] = a;
            s_win[m][1][n] = b;
            s_win[m][2][n] = s_y[m][n];
        }
        __syncthreads();
    }
}

extern "C" void kernel_launch(void* const* d_in, const int* in_sizes, int n_in,
                              void* d_out, int out_size) {
    const float* inputs = (const float*)d_in[0];
    const float* ln1_g  = (const float*)d_in[1];
    const float* ln1_b  = (const float*)d_in[2];
    const float* w1     = (const float*)d_in[3];
    const float* b1     = (const float*)d_in[4];
    const float* w2     = (const float*)d_in[5];
    const float* b2     = (const float*)d_in[6];
    const float* wu     = (const float*)d_in[7];
    const float* bu     = (const float*)d_in[8];
    const float* ln2_g  = (const float*)d_in[9];
    const float* ln2_b  = (const float*)d_in[10];
    const float* wbeta  = (const float*)d_in[11];
    const float* wd1    = (const float*)d_in[12];
    const float* bd1    = (const float*)d_in[13];
    const float* wd2    = (const float*)d_in[14];
    const float* bd2    = (const float*)d_in[15];
    const int*   fix    = (const int*)  d_in[16];
    float* out = (float*)d_out;

    cudaFuncSetAttribute(dps_kernel, cudaFuncAttributeMaxDynamicSharedMemorySize,
                         SMEM_BYTES);

    pack_kernel<<<8, 512>>>(wd2);
    dps_kernel<<<NCTA, NTHREADS, SMEM_BYTES>>>(inputs, ln1_g, ln1_b, w1, b1, w2, b2,
                                               wu, bu, ln2_g, ln2_b, wbeta,
                                               wd1, bd1, wd2, bd2, fix, out);
}